// round 7
// baseline (speedup 1.0000x reference)
#include <cuda_runtime.h>
#include <cstdint>

// ============================================================================
// DynamicConv1D: T=2048, B=16, C=512, H=8, R=64, K=7
//   phase 1: logits = query @ W  (32768 x 512)*(512 x 56), K-SPLIT in 2 halves,
//            raw partial logits -> g_part. Softmax deferred to phase 2.
//   phase 2: conv block sums the 2 partials, softmaxes (7-wide) while staging
//            weights, then out[t,b,h*64+r] = sum_kk w * xs[tl*512+h*448+r*7+kk]
// ============================================================================

#define T_DIM 2048
#define B_DIM 16
#define C_DIM 512
#define H_DIM 8
#define K_DIM 7

#define M_DIM   32768            // T*B rows
#define KSPLIT  2
#define KHALF   (C_DIM / KSPLIT) // 256
#define BKK     16               // k-tile depth
#define NTILE   (KHALF / BKK)    // 16
#define PART_OFF ((size_t)M_DIM * 64)

// raw partial logits: [kslice][row*64 + head*8 + j]  (j 0..6 used, 7 = pad)
__device__ float g_part[(size_t)KSPLIT * M_DIM * 64];

// ---------------------------------------------------------------------------
// Kernel 1: K-split GEMM. BM=128 rows, 256 threads = 8 warps, warp w == head w
// (B reads are warp-uniform broadcasts). Lane owns rows {4L..4L+3}: one
// LDS.128 -> two f32x2 packs, 14 FFMA2 per kk. Register-double-buffered
// tiles (BK=16), one __syncthreads per tile. A-transpose swizzle:
//   rp = row ^ 8*(f4&1) ^ 16*(f4>>1)  -> conflict-free STS, contiguous loads.
// ---------------------------------------------------------------------------
__device__ __forceinline__ unsigned long long fma2(unsigned long long a,
                                                   unsigned long long b,
                                                   unsigned long long c) {
    asm("fma.rn.f32x2 %0, %1, %2, %0;" : "+l"(c) : "l"(a), "l"(b));
    return c;
}

#define GEMM_SMEM (2 * (BKK * 128 + BKK * 64 * 2) * 4)   // 32768 B

__global__ __launch_bounds__(256, 3)
void gemm_kernel(const float* __restrict__ query,
                 const float* __restrict__ W) {
    extern __shared__ float smem[];
    float*  As[2] = { smem, smem + BKK * 128 };                       // 2 x 8 KB
    float2* Bs[2] = { (float2*)(smem + 2 * BKK * 128),
                      (float2*)(smem + 2 * BKK * 128) + BKK * 64 };   // 2 x 8 KB

    const int tid      = threadIdx.x;
    const int lane     = tid & 31;
    const int head     = tid >> 5;                 // warp id == head
    const int rowBlk   = blockIdx.x >> 1;
    const int ks       = blockIdx.x & 1;
    const int blockRow = rowBlk * 128;
    const int kbase    = ks * KHALF;

    unsigned long long acc[2][7];
    #pragma unroll
    for (int p = 0; p < 2; p++)
        #pragma unroll
        for (int j = 0; j < 7; j++) acc[p][j] = 0ULL;

    // per-thread tile-fragment indices (constant across tiles)
    const int aRow = tid >> 2;                 // 0..63  (first of 2, step 64)
    const int aF4  = tid & 3;                  // k-quad within tile
    const int aRp  = 8 * (aF4 & 1) + 16 * (aF4 >> 1);   // XOR mask for rows

    float4 pa[2];          // A prefetch: rows aRow, aRow+64
    float  pb[4];          // B prefetch: 4 slots

    // ---- prefetch + store helpers (macros keep reg lifetimes tight) ----
    #define LOAD_TILE(tt)                                                     \
    {                                                                         \
        int k0 = kbase + (tt) * BKK;                                          \
        pa[0] = *(const float4*)(query + (size_t)(blockRow + aRow) * C_DIM + k0 + aF4 * 4);      \
        pa[1] = *(const float4*)(query + (size_t)(blockRow + aRow + 64) * C_DIM + k0 + aF4 * 4); \
        _Pragma("unroll")                                                     \
        for (int l = 0; l < 4; l++) {                                         \
            int linear = tid + l * 256;                                       \
            int kk   = linear >> 6;                                           \
            int slot = linear & 63;                                           \
            int hs   = slot >> 3;                                             \
            int jj   = slot & 7;                                              \
            pb[l] = (jj < 7) ? W[(k0 + kk) * 56 + hs * 7 + jj] : 0.0f;        \
        }                                                                     \
    }

    #define STORE_TILE(buf)                                                   \
    {                                                                         \
        float* a_ = As[buf];                                                  \
        _Pragma("unroll")                                                     \
        for (int h2 = 0; h2 < 2; h2++) {                                      \
            int rp = (aRow + h2 * 64) ^ aRp;                                  \
            float4 v = pa[h2];                                                \
            a_[(4 * aF4 + 0) * 128 + rp] = v.x;                               \
            a_[(4 * aF4 + 1) * 128 + rp] = v.y;                               \
            a_[(4 * aF4 + 2) * 128 + rp] = v.z;                               \
            a_[(4 * aF4 + 3) * 128 + rp] = v.w;                               \
        }                                                                     \
        float2* b_ = Bs[buf];                                                 \
        _Pragma("unroll")                                                     \
        for (int l = 0; l < 4; l++)                                           \
            b_[tid + l * 256] = make_float2(pb[l], pb[l]);                    \
    }

    LOAD_TILE(0);
    STORE_TILE(0);
    __syncthreads();

    for (int t = 0; t < NTILE; t++) {
        const int cur = t & 1;
        if (t + 1 < NTILE) LOAD_TILE(t + 1);

        const float*  a_ = As[cur];
        const float2* b_ = Bs[cur];
        #pragma unroll
        for (int q = 0; q < 4; q++) {
            const int lx4 = 4 * (lane ^ (2 * (q & 1)) ^ (4 * (q >> 1)));
            #pragma unroll
            for (int j4 = 0; j4 < 4; j4++) {
                const int kk = 4 * q + j4;
                ulonglong2 a = *(const ulonglong2*)&a_[kk * 128 + lx4];
                const ulonglong2* bp = (const ulonglong2*)&b_[kk * 64 + head * 8];
                ulonglong2 b01 = bp[0], b23 = bp[1], b45 = bp[2], b67 = bp[3];
                unsigned long long b[7] = {b01.x, b01.y, b23.x, b23.y, b45.x, b45.y, b67.x};
                #pragma unroll
                for (int j = 0; j < 7; j++) {
                    acc[0][j] = fma2(a.x, b[j], acc[0][j]);
                    acc[1][j] = fma2(a.y, b[j], acc[1][j]);
                }
            }
        }
        if (t + 1 < NTILE) STORE_TILE(1 - cur);
        __syncthreads();
    }

    // ---- epilogue: store raw partial logits (padded to 8) ----
    float* base = g_part + (size_t)ks * PART_OFF;
    #pragma unroll
    for (int p = 0; p < 2; p++) {
        float lo[7], hi[7];
        #pragma unroll
        for (int j = 0; j < 7; j++) {
            unsigned int ulo, uhi;
            asm("mov.b64 {%0, %1}, %2;" : "=r"(ulo), "=r"(uhi) : "l"(acc[p][j]));
            lo[j] = __uint_as_float(ulo);
            hi[j] = __uint_as_float(uhi);
        }
        #pragma unroll
        for (int half = 0; half < 2; half++) {
            float* v = half ? hi : lo;
            int row = blockRow + 4 * lane + 2 * p + half;
            size_t n8 = (size_t)row * 64 + head * 8;
            *(float4*)&base[n8]     = make_float4(v[0], v[1], v[2], v[3]);
            *(float4*)&base[n8 + 4] = make_float4(v[4], v[5], v[6], 0.0f);
        }
    }
}

// ---------------------------------------------------------------------------
// Kernel 2: gathered conv (R1 known-good config: 43.8 us) + fused softmax in
// the weight-staging step. Block = (t-tile of 16, one b), 512 threads, 48 KB
// smem, 3 blocks/SM. Taps are 7 consecutive smem floats, lane stride 7 words
// -> conflict-free (gcd(7,32)=1).
// ---------------------------------------------------------------------------
#define TT 16
#define XS_ROWS (TT + K_DIM - 1)            // 22
#define SMEM_CONV ((XS_ROWS * C_DIM + TT * 64) * 4)   // 49152 bytes

__global__ __launch_bounds__(512, 3)
void conv_kernel(const float* __restrict__ x, float* __restrict__ out) {
    extern __shared__ float smem[];
    float* xs = smem;                        // 22*512
    float* ws = smem + XS_ROWS * C_DIM;      // 16*64

    const int tid = threadIdx.x;
    const int t0  = (blockIdx.x >> 4) * TT;
    const int b   = blockIdx.x & 15;

    // ---- stage weights: sum the 2 k-split partials, softmax over 7 taps ----
    if (tid < TT * 8) {
        int tl = tid >> 3;                   // 0..15
        int h  = tid & 7;                    // 0..7
        size_t n8 = ((size_t)(t0 + tl) * B_DIM + b) * 64 + h * 8;
        float4 x0 = *(const float4*)(g_part + n8);
        float4 x1 = *(const float4*)(g_part + n8 + 4);
        float4 y0 = *(const float4*)(g_part + PART_OFF + n8);
        float4 y1 = *(const float4*)(g_part + PART_OFF + n8 + 4);
        float v[7] = { x0.x + y0.x, x0.y + y0.y, x0.z + y0.z, x0.w + y0.w,
                       x1.x + y1.x, x1.y + y1.y, x1.z + y1.z };
        float m = v[0];
        #pragma unroll
        for (int j = 1; j < 7; j++) m = fmaxf(m, v[j]);
        float e[7], s = 0.0f;
        #pragma unroll
        for (int j = 0; j < 7; j++) { e[j] = __expf(v[j] - m); s += e[j]; }
        float inv = 1.0f / s;
        *(float4*)&ws[tl * 64 + h * 8]     = make_float4(e[0]*inv, e[1]*inv, e[2]*inv, e[3]*inv);
        *(float4*)&ws[tl * 64 + h * 8 + 4] = make_float4(e[4]*inv, e[5]*inv, e[6]*inv, 0.0f);
    }
    // ---- stage x tile with halo, zero-padded at sequence edges ----
    for (int linear = tid; linear < XS_ROWS * (C_DIM / 4); linear += 512) {
        int irow = linear >> 7;              // 0..21
        int c4   = linear & 127;
        int tg   = t0 - 3 + irow;
        float4 v = make_float4(0.0f, 0.0f, 0.0f, 0.0f);
        if (tg >= 0 && tg < T_DIM)
            v = *(const float4*)(x + ((size_t)tg * B_DIM + b) * C_DIM + c4 * 4);
        *(float4*)&xs[irow * C_DIM + c4 * 4] = v;
    }
    __syncthreads();

    const int c  = tid;
    const int h  = c >> 6;                   // uniform per warp
    const int fb = h * 448 + (c & 63) * 7;   // flat offset of first tap

    #pragma unroll 4
    for (int tl = 0; tl < TT; tl++) {
        const float4* wp = (const float4*)&ws[tl * 64 + h * 8];   // broadcast
        float4 w0 = wp[0];
        float4 w1 = wp[1];
        const float* xp = &xs[tl * C_DIM + fb];   // 7 consecutive floats
        float acc;
        acc = w0.x * xp[0];
        acc = fmaf(w0.y, xp[1], acc);
        acc = fmaf(w0.z, xp[2], acc);
        acc = fmaf(w0.w, xp[3], acc);
        acc = fmaf(w1.x, xp[4], acc);
        acc = fmaf(w1.y, xp[5], acc);
        acc = fmaf(w1.z, xp[6], acc);
        out[((size_t)(t0 + tl) * B_DIM + b) * C_DIM + c] = acc;
    }
}

// ---------------------------------------------------------------------------
extern "C" void kernel_launch(void* const* d_in, const int* in_sizes, int n_in,
                              void* d_out, int out_size) {
    const float* x     = (const float*)d_in[0];
    const float* query = (const float*)d_in[1];
    const float* W     = (const float*)d_in[2];
    float* out         = (float*)d_out;

    cudaFuncSetAttribute(conv_kernel, cudaFuncAttributeMaxDynamicSharedMemorySize, SMEM_CONV);

    // phase 1: (32768/128) row-blocks x 2 k-slices = 512 blocks x 256 threads
    gemm_kernel<<<512, 256, GEMM_SMEM>>>(query, W);
    // phase 2: 128 t-tiles x 16 batches
    conv_kernel<<<(T_DIM / TT) * B_DIM, 512, SMEM_CONV>>>(x, out);
}

// round 8
// speedup vs baseline: 1.3503x; 1.3503x over previous
#include <cuda_runtime.h>
#include <cstdint>

// ============================================================================
// DynamicConv1D: T=2048, B=16, C=512, H=8, R=64, K=7
//  phase 0: prep  — split W (512x56, padded to n=64) into tf32 hi/lo MMA
//                   fragments, stored fragment-ordered in g_Bfrag.
//  phase 1: gemm  — logits = query @ W via mma.sync m16n8k8 tf32 (3-term
//                   split = fp32-accurate). Head j == n8 tile j. Softmax over
//                   the 7 taps fused in epilogue via quad shuffles.
//  phase 2: conv  — out[t,b,h*64+r] = sum_kk w * xs[tl*512 + h*448 + r*7 + kk]
// ============================================================================

#define T_DIM 2048
#define B_DIM 16
#define C_DIM 512
#define H_DIM 8
#define K_DIM 7

// softmaxed weights: [row(=t*16+b)][head*8 + slot]  (slot 0..6 used)
__device__ float g_weights[(size_t)T_DIM * B_DIM * 64];
// B fragments: [kstep 0..63][j 0..7][lane 0..31] = (b0h, b1h, b0l, b1l)
__device__ float4 g_Bfrag[64 * 8 * 32];

// ---------------------------------------------------------------------------
__device__ __forceinline__ float tf32_rna(float v) {
    unsigned int u;
    asm("cvt.rna.tf32.f32 %0, %1;" : "=r"(u) : "f"(v));
    return __uint_as_float(u);
}

__device__ __forceinline__ void mma_tf32(float* d, const unsigned int* a,
                                         unsigned int b0, unsigned int b1) {
    asm volatile(
        "mma.sync.aligned.m16n8k8.row.col.f32.tf32.tf32.f32 "
        "{%0,%1,%2,%3}, {%4,%5,%6,%7}, {%8,%9}, {%0,%1,%2,%3};"
        : "+f"(d[0]), "+f"(d[1]), "+f"(d[2]), "+f"(d[3])
        : "r"(a[0]), "r"(a[1]), "r"(a[2]), "r"(a[3]), "r"(b0), "r"(b1));
}

__device__ __forceinline__ void cp16(void* smem_dst, const void* gmem_src) {
    unsigned int d = (unsigned int)__cvta_generic_to_shared(smem_dst);
    asm volatile("cp.async.ca.shared.global [%0], [%1], 16;" :: "r"(d), "l"(gmem_src));
}

// ---------------------------------------------------------------------------
// Kernel 0: build tf32 hi/lo B fragments. idx = (ks*8 + j)*32 + lane.
// b0 = B[k = ks*8+tg][n = j*8+g], b1 = same k+4. n->  tap g of head j (g<7).
// ---------------------------------------------------------------------------
__global__ void prep_b_kernel(const float* __restrict__ W) {
    int idx  = blockIdx.x * 256 + threadIdx.x;      // 0..16383
    int lane = idx & 31;
    int j    = (idx >> 5) & 7;
    int ks   = idx >> 8;
    int tg   = lane & 3;
    int g    = lane >> 2;
    int k0   = ks * 8 + tg;
    float b0 = (g < 7) ? W[k0 * 56 + j * 7 + g] : 0.0f;
    float b1 = (g < 7) ? W[(k0 + 4) * 56 + j * 7 + g] : 0.0f;
    float b0h = tf32_rna(b0), b0l = tf32_rna(b0 - b0h);
    float b1h = tf32_rna(b1), b1l = tf32_rna(b1 - b1h);
    g_Bfrag[idx] = make_float4(b0h, b1h, b0l, b1l);
}

// ---------------------------------------------------------------------------
// Kernel 1: GEMM M=32768 N=64 K=512 + fused softmax.
// 128 threads = 4 warps; warp w owns rows w*32..w*32+31 (2 m16 tiles) x n64.
// BK=32 (4 k-steps of 8), cp.async double-buffered A (row-major stride 36:
// A-frag LDS.32 banks = 4g+tg, conflict-free) and B (fragment-ordered copy).
// Per k-step: 2 m-tiles x 8 heads x 3 split-terms = 48 MMAs.
// ---------------------------------------------------------------------------
#define AS_STRIDE 36
#define AS_WORDS  (128 * AS_STRIDE)                 // 4608 words
#define BS_ELEMS  (4 * 8 * 32)                      // float4 per tile = 1024
#define GEMM_SMEM (2 * AS_WORDS * 4 + 2 * BS_ELEMS * 16)   // 69632 B

__global__ __launch_bounds__(128, 3)
void gemm_softmax_kernel(const float* __restrict__ query) {
    extern __shared__ float smem[];
    float*  As[2] = { smem, smem + AS_WORDS };
    float4* Bs[2] = { (float4*)(smem + 2 * AS_WORDS),
                      (float4*)(smem + 2 * AS_WORDS) + BS_ELEMS };

    const int tid  = threadIdx.x;
    const int wrp  = tid >> 5;
    const int lane = tid & 31;
    const int g    = lane >> 2;
    const int tg   = lane & 3;
    const int blockRow = blockIdx.x * 128;

    float d[2][8][4];
    #pragma unroll
    for (int mt = 0; mt < 2; mt++)
        #pragma unroll
        for (int j = 0; j < 8; j++)
            #pragma unroll
            for (int q = 0; q < 4; q++) d[mt][j][q] = 0.0f;

    #define STAGE(t, buf)                                                     \
    {                                                                         \
        int k0 = (t) * 32;                                                    \
        _Pragma("unroll")                                                     \
        for (int i = 0; i < 8; i++) {                                         \
            int linear = tid + i * 128;             /* 0..1023 */             \
            int row    = linear >> 3;                                         \
            int f4     = linear & 7;                                          \
            cp16(&As[buf][row * AS_STRIDE + f4 * 4],                          \
                 query + (size_t)(blockRow + row) * C_DIM + k0 + f4 * 4);     \
        }                                                                     \
        const float4* src = g_Bfrag + (size_t)(t) * BS_ELEMS;                 \
        _Pragma("unroll")                                                     \
        for (int i = 0; i < 8; i++) {                                         \
            int linear = tid + i * 128;                                       \
            cp16(&Bs[buf][linear], src + linear);                             \
        }                                                                     \
        asm volatile("cp.async.commit_group;");                               \
    }

    STAGE(0, 0);
    STAGE(1, 1);

    for (int t = 0; t < 16; t++) {
        if (t < 15) asm volatile("cp.async.wait_group 1;");
        else        asm volatile("cp.async.wait_group 0;");
        __syncthreads();
        const int buf = t & 1;
        const float*  a_ = As[buf];
        const float4* b_ = Bs[buf];

        #pragma unroll
        for (int ks = 0; ks < 4; ks++) {
            // ---- A fragments + tf32 split, 2 m16 tiles ----
            unsigned int ah[2][4], al[2][4];
            #pragma unroll
            for (int mt = 0; mt < 2; mt++) {
                int rbase = wrp * 32 + mt * 16;
                int col   = ks * 8 + tg;
                float a0 = a_[(rbase + g)     * AS_STRIDE + col];
                float a1 = a_[(rbase + g + 8) * AS_STRIDE + col];
                float a2 = a_[(rbase + g)     * AS_STRIDE + col + 4];
                float a3 = a_[(rbase + g + 8) * AS_STRIDE + col + 4];
                float h0 = tf32_rna(a0), h1 = tf32_rna(a1);
                float h2 = tf32_rna(a2), h3 = tf32_rna(a3);
                ah[mt][0] = __float_as_uint(h0); al[mt][0] = __float_as_uint(tf32_rna(a0 - h0));
                ah[mt][1] = __float_as_uint(h1); al[mt][1] = __float_as_uint(tf32_rna(a1 - h1));
                ah[mt][2] = __float_as_uint(h2); al[mt][2] = __float_as_uint(tf32_rna(a2 - h2));
                ah[mt][3] = __float_as_uint(h3); al[mt][3] = __float_as_uint(tf32_rna(a3 - h3));
            }
            #pragma unroll
            for (int j = 0; j < 8; j++) {
                float4 bv = b_[(ks * 8 + j) * 32 + lane];
                unsigned int b0h = __float_as_uint(bv.x), b1h = __float_as_uint(bv.y);
                unsigned int b0l = __float_as_uint(bv.z), b1l = __float_as_uint(bv.w);
                #pragma unroll
                for (int mt = 0; mt < 2; mt++) {
                    mma_tf32(d[mt][j], ah[mt], b0h, b1h);   // hi*hi
                    mma_tf32(d[mt][j], al[mt], b0h, b1h);   // lo*hi
                    mma_tf32(d[mt][j], ah[mt], b0l, b1l);   // hi*lo
                }
            }
        }
        __syncthreads();
        if (t + 2 < 16) STAGE(t + 2, buf);
    }

    // ---- epilogue: softmax per (row, head) across the tg-quad, store ----
    // lane holds cols {2tg, 2tg+1} of each head; tap 7 (tg==3, second col)
    // is the N-pad and is excluded from max/sum, its weight stored as 0.
    #pragma unroll
    for (int mt = 0; mt < 2; mt++) {
        #pragma unroll
        for (int rh = 0; rh < 2; rh++) {
            int row = blockRow + wrp * 32 + mt * 16 + g + rh * 8;
            float* wrow = g_weights + (size_t)row * 64;
            #pragma unroll
            for (int j = 0; j < 8; j++) {
                float c0 = d[mt][j][rh * 2 + 0];
                float c1 = d[mt][j][rh * 2 + 1];
                bool pad = (tg == 3);
                float m = pad ? c0 : fmaxf(c0, c1);
                m = fmaxf(m, __shfl_xor_sync(0xffffffffu, m, 1));
                m = fmaxf(m, __shfl_xor_sync(0xffffffffu, m, 2));
                float e0 = __expf(c0 - m);
                float e1 = pad ? 0.0f : __expf(c1 - m);
                float s = e0 + e1;
                s += __shfl_xor_sync(0xffffffffu, s, 1);
                s += __shfl_xor_sync(0xffffffffu, s, 2);
                float inv = 1.0f / s;
                *(float2*)&wrow[j * 8 + 2 * tg] = make_float2(e0 * inv, e1 * inv);
            }
        }
    }
}

// ---------------------------------------------------------------------------
// Kernel 2: gathered conv (known-good 43.8 us config). Block = (t-tile of 16,
// one b), 512 threads, 48 KB smem, 3 blocks/SM. Taps are 7 consecutive smem
// floats, lane stride 7 words -> conflict-free (gcd(7,32)=1).
// ---------------------------------------------------------------------------
#define TT 16
#define XS_ROWS (TT + K_DIM - 1)            // 22
#define SMEM_CONV ((XS_ROWS * C_DIM + TT * 64) * 4)   // 49152 bytes

__global__ __launch_bounds__(512, 3)
void conv_kernel(const float* __restrict__ x, float* __restrict__ out) {
    extern __shared__ float smem[];
    float* xs = smem;                        // 22*512
    float* ws = smem + XS_ROWS * C_DIM;      // 16*64

    const int tid = threadIdx.x;
    const int t0  = (blockIdx.x >> 4) * TT;
    const int b   = blockIdx.x & 15;

    // ---- stage weights: per t, 64 contiguous floats (8 heads x 8 slots) ----
    if (tid < TT * 16) {
        int tl = tid >> 4;                   // 0..15
        int f4 = tid & 15;                   // 0..15
        const float4* src = (const float4*)(g_weights + ((size_t)(t0 + tl) * B_DIM + b) * 64);
        *(float4*)&ws[tl * 64 + f4 * 4] = src[f4];
    }
    // ---- stage x tile with halo, zero-padded at sequence edges ----
    for (int linear = tid; linear < XS_ROWS * (C_DIM / 4); linear += 512) {
        int irow = linear >> 7;              // 0..21
        int c4   = linear & 127;
        int tg   = t0 - 3 + irow;
        float4 v = make_float4(0.0f, 0.0f, 0.0f, 0.0f);
        if (tg >= 0 && tg < T_DIM)
            v = *(const float4*)(x + ((size_t)tg * B_DIM + b) * C_DIM + c4 * 4);
        *(float4*)&xs[irow * C_DIM + c4 * 4] = v;
    }
    __syncthreads();

    const int c  = tid;
    const int h  = c >> 6;                   // uniform per warp
    const int fb = h * 448 + (c & 63) * 7;   // flat offset of first tap

    #pragma unroll 4
    for (int tl = 0; tl < TT; tl++) {
        const float4* wp = (const float4*)&ws[tl * 64 + h * 8];   // broadcast
        float4 w0 = wp[0];
        float4 w1 = wp[1];
        const float* xp = &xs[tl * C_DIM + fb];   // 7 consecutive floats
        float acc;
        acc = w0.x * xp[0];
        acc = fmaf(w0.y, xp[1], acc);
        acc = fmaf(w0.z, xp[2], acc);
        acc = fmaf(w0.w, xp[3], acc);
        acc = fmaf(w1.x, xp[4], acc);
        acc = fmaf(w1.y, xp[5], acc);
        acc = fmaf(w1.z, xp[6], acc);
        out[((size_t)(t0 + tl) * B_DIM + b) * C_DIM + c] = acc;
    }
}

// ---------------------------------------------------------------------------
extern "C" void kernel_launch(void* const* d_in, const int* in_sizes, int n_in,
                              void* d_out, int out_size) {
    const float* x     = (const float*)d_in[0];
    const float* query = (const float*)d_in[1];
    const float* W     = (const float*)d_in[2];
    float* out         = (float*)d_out;

    cudaFuncSetAttribute(gemm_softmax_kernel, cudaFuncAttributeMaxDynamicSharedMemorySize, GEMM_SMEM);
    cudaFuncSetAttribute(conv_kernel, cudaFuncAttributeMaxDynamicSharedMemorySize, SMEM_CONV);

    // phase 0: 16384 fragment entries / 256
    prep_b_kernel<<<64, 256>>>(W);
    // phase 1: 32768 rows / 128 = 256 blocks x 128 threads
    gemm_softmax_kernel<<<256, 128, GEMM_SMEM>>>(query);
    // phase 2: 128 t-tiles x 16 batches
    conv_kernel<<<(T_DIM / TT) * B_DIM, 512, SMEM_CONV>>>(x, out);
}

// round 9
// speedup vs baseline: 1.6002x; 1.1850x over previous
#include <cuda_runtime.h>
#include <cstdint>

// ============================================================================
// DynamicConv1D: T=2048, B=16, C=512, H=8, R=64, K=7
//  phase 0: prep  — split W (512x56, padded to n=64) into tf32 hi/lo MMA
//                   fragments, stored fragment-ordered in g_Bfrag.
//  phase 1: gemm  — logits = query @ W via mma.sync m16n8k8 tf32 (3-term
//                   split = fp32-accurate). Head j == n8 tile j. Softmax over
//                   the 7 taps fused in epilogue via quad shuffles.
//  phase 2: conv  — out[t,b,h*64+r] = sum_kk w * xs[tl*512 + h*448 + r*7 + kk]
// ============================================================================

#define T_DIM 2048
#define B_DIM 16
#define C_DIM 512
#define H_DIM 8
#define K_DIM 7

// softmaxed weights: [row(=t*16+b)][head*8 + slot]  (slot 0..6 used)
__device__ float g_weights[(size_t)T_DIM * B_DIM * 64];
// B fragments: [kstep 0..63][j 0..7][lane 0..31] = (b0h, b1h, b0l, b1l)
__device__ float4 g_Bfrag[64 * 8 * 32];

// ---------------------------------------------------------------------------
__device__ __forceinline__ float tf32_rna(float v) {
    unsigned int u;
    asm("cvt.rna.tf32.f32 %0, %1;" : "=r"(u) : "f"(v));
    return __uint_as_float(u);
}

__device__ __forceinline__ void mma_tf32(float* d, const unsigned int* a,
                                         unsigned int b0, unsigned int b1) {
    asm volatile(
        "mma.sync.aligned.m16n8k8.row.col.f32.tf32.tf32.f32 "
        "{%0,%1,%2,%3}, {%4,%5,%6,%7}, {%8,%9}, {%0,%1,%2,%3};"
        : "+f"(d[0]), "+f"(d[1]), "+f"(d[2]), "+f"(d[3])
        : "r"(a[0]), "r"(a[1]), "r"(a[2]), "r"(a[3]), "r"(b0), "r"(b1));
}

__device__ __forceinline__ void cp16(void* smem_dst, const void* gmem_src) {
    unsigned int d = (unsigned int)__cvta_generic_to_shared(smem_dst);
    asm volatile("cp.async.ca.shared.global [%0], [%1], 16;" :: "r"(d), "l"(gmem_src));
}

// ---------------------------------------------------------------------------
// Kernel 0: build tf32 hi/lo B fragments. idx = (ks*8 + j)*32 + lane.
// ---------------------------------------------------------------------------
__global__ void prep_b_kernel(const float* __restrict__ W) {
    int idx  = blockIdx.x * 256 + threadIdx.x;      // 0..16383
    int lane = idx & 31;
    int j    = (idx >> 5) & 7;
    int ks   = idx >> 8;
    int tg   = lane & 3;
    int g    = lane >> 2;
    int k0   = ks * 8 + tg;
    float b0 = (g < 7) ? W[k0 * 56 + j * 7 + g] : 0.0f;
    float b1 = (g < 7) ? W[(k0 + 4) * 56 + j * 7 + g] : 0.0f;
    float b0h = tf32_rna(b0), b0l = tf32_rna(b0 - b0h);
    float b1h = tf32_rna(b1), b1l = tf32_rna(b1 - b1h);
    g_Bfrag[idx] = make_float4(b0h, b1h, b0l, b1l);
}

// ---------------------------------------------------------------------------
// Kernel 1: GEMM M=32768 N=64 K=512 + fused softmax.
// 256 threads = 8 warps; warp w owns ONE m16 tile (rows w*16..w*16+15) x n64.
// BK=32 (4 k-steps of 8), cp.async double-buffered A (row-major stride 36:
// A-frag LDS.32 banks = 4g+tg, conflict-free) and B (fragment-ordered copy).
// Per warp-kstep: 4 LDS.32 + 12 cvt + 8 LDS.128 + 24 MMA.
// ---------------------------------------------------------------------------
#define AS_STRIDE 36
#define AS_WORDS  (128 * AS_STRIDE)                 // 4608 words
#define BS_ELEMS  (4 * 8 * 32)                      // float4 per tile = 1024
#define GEMM_SMEM (2 * AS_WORDS * 4 + 2 * BS_ELEMS * 16)   // 69632 B

__global__ __launch_bounds__(256, 2)
void gemm_softmax_kernel(const float* __restrict__ query) {
    extern __shared__ float smem[];
    float*  As[2] = { smem, smem + AS_WORDS };
    float4* Bs[2] = { (float4*)(smem + 2 * AS_WORDS),
                      (float4*)(smem + 2 * AS_WORDS) + BS_ELEMS };

    const int tid  = threadIdx.x;
    const int wrp  = tid >> 5;
    const int lane = tid & 31;
    const int g    = lane >> 2;
    const int tg   = lane & 3;
    const int blockRow = blockIdx.x * 128;

    float d[8][4];
    #pragma unroll
    for (int j = 0; j < 8; j++)
        #pragma unroll
        for (int q = 0; q < 4; q++) d[j][q] = 0.0f;

    #define STAGE(t, buf)                                                     \
    {                                                                         \
        int k0 = (t) * 32;                                                    \
        _Pragma("unroll")                                                     \
        for (int i = 0; i < 4; i++) {                                         \
            int linear = tid + i * 256;             /* 0..1023 */             \
            int row    = linear >> 3;                                         \
            int f4     = linear & 7;                                          \
            cp16(&As[buf][row * AS_STRIDE + f4 * 4],                          \
                 query + (size_t)(blockRow + row) * C_DIM + k0 + f4 * 4);     \
        }                                                                     \
        const float4* src = g_Bfrag + (size_t)(t) * BS_ELEMS;                 \
        _Pragma("unroll")                                                     \
        for (int i = 0; i < 4; i++) {                                         \
            int linear = tid + i * 256;                                       \
            cp16(&Bs[buf][linear], src + linear);                             \
        }                                                                     \
        asm volatile("cp.async.commit_group;");                               \
    }

    STAGE(0, 0);
    STAGE(1, 1);

    for (int t = 0; t < 16; t++) {
        if (t < 15) asm volatile("cp.async.wait_group 1;");
        else        asm volatile("cp.async.wait_group 0;");
        __syncthreads();
        const int buf = t & 1;
        const float*  a_ = As[buf];
        const float4* b_ = Bs[buf];

        #pragma unroll
        for (int ks = 0; ks < 4; ks++) {
            // ---- A fragment + tf32 split, one m16 tile ----
            const int rbase = wrp * 16;
            const int col   = ks * 8 + tg;
            float a0 = a_[(rbase + g)     * AS_STRIDE + col];
            float a1 = a_[(rbase + g + 8) * AS_STRIDE + col];
            float a2 = a_[(rbase + g)     * AS_STRIDE + col + 4];
            float a3 = a_[(rbase + g + 8) * AS_STRIDE + col + 4];
            float h0 = tf32_rna(a0), h1 = tf32_rna(a1);
            float h2 = tf32_rna(a2), h3 = tf32_rna(a3);
            unsigned int ah[4], al[4];
            ah[0] = __float_as_uint(h0); al[0] = __float_as_uint(tf32_rna(a0 - h0));
            ah[1] = __float_as_uint(h1); al[1] = __float_as_uint(tf32_rna(a1 - h1));
            ah[2] = __float_as_uint(h2); al[2] = __float_as_uint(tf32_rna(a2 - h2));
            ah[3] = __float_as_uint(h3); al[3] = __float_as_uint(tf32_rna(a3 - h3));
            #pragma unroll
            for (int j = 0; j < 8; j++) {
                float4 bv = b_[(ks * 8 + j) * 32 + lane];
                unsigned int b0h = __float_as_uint(bv.x), b1h = __float_as_uint(bv.y);
                unsigned int b0l = __float_as_uint(bv.z), b1l = __float_as_uint(bv.w);
                mma_tf32(d[j], ah, b0h, b1h);   // hi*hi
                mma_tf32(d[j], al, b0h, b1h);   // lo*hi
                mma_tf32(d[j], ah, b0l, b1l);   // hi*lo
            }
        }
        __syncthreads();
        if (t + 2 < 16) STAGE(t + 2, buf);
    }

    // ---- epilogue: softmax per (row, head) across the tg-quad, store ----
    // lane holds cols {2tg, 2tg+1}; tap 7 (tg==3, second col) is the N-pad:
    // excluded from max/sum, stored as 0.
    #pragma unroll
    for (int rh = 0; rh < 2; rh++) {
        int row = blockRow + wrp * 16 + g + rh * 8;
        float* wrow = g_weights + (size_t)row * 64;
        #pragma unroll
        for (int j = 0; j < 8; j++) {
            float c0 = d[j][rh * 2 + 0];
            float c1 = d[j][rh * 2 + 1];
            bool pad = (tg == 3);
            float m = pad ? c0 : fmaxf(c0, c1);
            m = fmaxf(m, __shfl_xor_sync(0xffffffffu, m, 1));
            m = fmaxf(m, __shfl_xor_sync(0xffffffffu, m, 2));
            float e0 = __expf(c0 - m);
            float e1 = pad ? 0.0f : __expf(c1 - m);
            float s = e0 + e1;
            s += __shfl_xor_sync(0xffffffffu, s, 1);
            s += __shfl_xor_sync(0xffffffffu, s, 2);
            float inv = 1.0f / s;
            *(float2*)&wrow[j * 8 + 2 * tg] = make_float2(e0 * inv, e1 * inv);
        }
    }
}

// ---------------------------------------------------------------------------
// Kernel 2: gathered conv. Block = (t-tile of 16, one b), 512 threads, 48 KB
// smem, 3 blocks/SM. Taps are 7 consecutive smem floats, lane stride 7 words
// -> conflict-free (gcd(7,32)=1). Accumulation tree-shaped (dep chain 16 cyc
// instead of 28) since the kernel is latency/issue-bound.
// ---------------------------------------------------------------------------
#define TT 16
#define XS_ROWS (TT + K_DIM - 1)            // 22
#define SMEM_CONV ((XS_ROWS * C_DIM + TT * 64) * 4)   // 49152 bytes

__global__ __launch_bounds__(512, 3)
void conv_kernel(const float* __restrict__ x, float* __restrict__ out) {
    extern __shared__ float smem[];
    float* xs = smem;                        // 22*512
    float* ws = smem + XS_ROWS * C_DIM;      // 16*64

    const int tid = threadIdx.x;
    const int t0  = (blockIdx.x >> 4) * TT;
    const int b   = blockIdx.x & 15;

    // ---- stage weights: per t, 64 contiguous floats (8 heads x 8 slots) ----
    if (tid < TT * 16) {
        int tl = tid >> 4;                   // 0..15
        int f4 = tid & 15;                   // 0..15
        const float4* src = (const float4*)(g_weights + ((size_t)(t0 + tl) * B_DIM + b) * 64);
        *(float4*)&ws[tl * 64 + f4 * 4] = src[f4];
    }
    // ---- stage x tile with halo, zero-padded at sequence edges ----
    for (int linear = tid; linear < XS_ROWS * (C_DIM / 4); linear += 512) {
        int irow = linear >> 7;              // 0..21
        int c4   = linear & 127;
        int tg   = t0 - 3 + irow;
        float4 v = make_float4(0.0f, 0.0f, 0.0f, 0.0f);
        if (tg >= 0 && tg < T_DIM)
            v = *(const float4*)(x + ((size_t)tg * B_DIM + b) * C_DIM + c4 * 4);
        *(float4*)&xs[irow * C_DIM + c4 * 4] = v;
    }
    __syncthreads();

    const int c  = tid;
    const int h  = c >> 6;                   // uniform per warp
    const int fb = h * 448 + (c & 63) * 7;   // flat offset of first tap

    #pragma unroll 4
    for (int tl = 0; tl < TT; tl++) {
        const float4* wp = (const float4*)&ws[tl * 64 + h * 8];   // broadcast
        float4 w0 = wp[0];
        float4 w1 = wp[1];
        const float* xp = &xs[tl * C_DIM + fb];   // 7 consecutive floats
        float p01 = w0.x * xp[0];
        p01 = fmaf(w0.y, xp[1], p01);
        float p23 = w0.z * xp[2];
        p23 = fmaf(w0.w, xp[3], p23);
        float p45 = w1.x * xp[4];
        p45 = fmaf(w1.y, xp[5], p45);
        float p6  = w1.z * xp[6];
        float acc = (p01 + p23) + (p45 + p6);
        out[((size_t)(t0 + tl) * B_DIM + b) * C_DIM + c] = acc;
    }
}

// ---------------------------------------------------------------------------
extern "C" void kernel_launch(void* const* d_in, const int* in_sizes, int n_in,
                              void* d_out, int out_size) {
    const float* x     = (const float*)d_in[0];
    const float* query = (const float*)d_in[1];
    const float* W     = (const float*)d_in[2];
    float* out         = (float*)d_out;

    cudaFuncSetAttribute(gemm_softmax_kernel, cudaFuncAttributeMaxDynamicSharedMemorySize, GEMM_SMEM);
    cudaFuncSetAttribute(conv_kernel, cudaFuncAttributeMaxDynamicSharedMemorySize, SMEM_CONV);

    // phase 0: 16384 fragment entries / 256
    prep_b_kernel<<<64, 256>>>(W);
    // phase 1: 32768 rows / 128 = 256 blocks x 256 threads
    gemm_softmax_kernel<<<256, 256, GEMM_SMEM>>>(query);
    // phase 2: 128 t-tiles x 16 batches
    conv_kernel<<<(T_DIM / TT) * B_DIM, 512, SMEM_CONV>>>(x, out);
}